// round 1
// baseline (speedup 1.0000x reference)
#include <cuda_runtime.h>
#include <math.h>

// Problem constants
#define B_    16
#define S_    2048
#define D_    1024
#define H_    16
#define CLIP_ 8
#define NC_   256
#define DK_   64

static const size_t TOK   = (size_t)B_ * S_;   // 32768 tokens
static const size_t ELEMS = TOK * D_;          // 33,554,432 floats per activation

// Scratch (static __device__ globals — sanctioned alloc-free scratch path)
__device__ float g_sq[ELEMS];
__device__ float g_sk[ELEMS];
__device__ float g_sv[ELEMS];
__device__ float g_tq[ELEMS];
__device__ float g_tk[ELEMS];
__device__ float g_tv[ELEMS];
__device__ float g_sa[ELEMS];
__device__ float g_ta[ELEMS];
__device__ float g_m1[D_ * D_];
__device__ float g_m2[D_ * D_];
__device__ float g_beff[D_];

// ---------------------------------------------------------------------------
// Generic fp32 GEMM:  C[M,N] = A[M,K] @ W[K,N] (+ bias[N]) (+ Cin[M,N])
// 128x128 tile, BK=8, 256 threads, 8x8 per-thread microtile.
// All shapes here are multiples of 128/8 — no bounds checks needed.
// ---------------------------------------------------------------------------
__global__ __launch_bounds__(256)
void gemm128(const float* __restrict__ A, const float* __restrict__ W,
             const float* __restrict__ bias, const float* __restrict__ Cin,
             float* __restrict__ C, int M, int N, int K)
{
    __shared__ float As[8][128];
    __shared__ float Bs[8][128];

    const int tid = threadIdx.x;
    const int tx = tid & 15;
    const int ty = tid >> 4;
    const int bx = blockIdx.x, by = blockIdx.y;

    float acc[8][8];
#pragma unroll
    for (int i = 0; i < 8; ++i)
#pragma unroll
        for (int j = 0; j < 8; ++j) acc[i][j] = 0.f;

    const float* Ab = A + (size_t)by * 128 * K;
    const float* Wb = W + (size_t)bx * 128;

    const int aRow = tid >> 1;
    const int aCol = (tid & 1) * 4;
    const int bRow = tid >> 5;
    const int bCol = (tid & 31) * 4;

    for (int k0 = 0; k0 < K; k0 += 8) {
        float4 av = *(const float4*)(Ab + (size_t)aRow * K + (k0 + aCol));
        float4 bv = *(const float4*)(Wb + (size_t)(k0 + bRow) * N + bCol);
        __syncthreads();
        As[aCol + 0][aRow] = av.x;
        As[aCol + 1][aRow] = av.y;
        As[aCol + 2][aRow] = av.z;
        As[aCol + 3][aRow] = av.w;
        *(float4*)&Bs[bRow][bCol] = bv;
        __syncthreads();
#pragma unroll
        for (int kk = 0; kk < 8; ++kk) {
            float a[8], b[8];
            *(float4*)&a[0] = *(const float4*)&As[kk][ty * 8];
            *(float4*)&a[4] = *(const float4*)&As[kk][ty * 8 + 4];
            *(float4*)&b[0] = *(const float4*)&Bs[kk][tx * 8];
            *(float4*)&b[4] = *(const float4*)&Bs[kk][tx * 8 + 4];
#pragma unroll
            for (int i = 0; i < 8; ++i)
#pragma unroll
                for (int j = 0; j < 8; ++j)
                    acc[i][j] += a[i] * b[j];
        }
    }

    const int col0 = bx * 128 + tx * 8;
    float bsum[8];
    if (bias) {
        *(float4*)&bsum[0] = *(const float4*)(bias + col0);
        *(float4*)&bsum[4] = *(const float4*)(bias + col0 + 4);
    } else {
#pragma unroll
        for (int j = 0; j < 8; ++j) bsum[j] = 0.f;
    }

#pragma unroll
    for (int i = 0; i < 8; ++i) {
        size_t row = (size_t)by * 128 + ty * 8 + i;
        float* cp = C + row * N + col0;
        float v[8];
#pragma unroll
        for (int j = 0; j < 8; ++j) v[j] = acc[i][j] + bsum[j];
        if (Cin) {
            const float* ci = Cin + row * N + col0;
            float4 c0 = *(const float4*)ci;
            float4 c1 = *(const float4*)(ci + 4);
            v[0] += c0.x; v[1] += c0.y; v[2] += c0.z; v[3] += c0.w;
            v[4] += c1.x; v[5] += c1.y; v[6] += c1.z; v[7] += c1.w;
        }
        *(float4*)cp = make_float4(v[0], v[1], v[2], v[3]);
        *(float4*)(cp + 4) = make_float4(v[4], v[5], v[6], v[7]);
    }
}

// ---------------------------------------------------------------------------
// Effective fuse bias: beff[n] = fuse_b[n] + sum_k sa_o_b[k]*fuse_w[k][n]
//                               + sum_k ta_o_b[k]*fuse_w[1024+k][n]
// ---------------------------------------------------------------------------
__global__ void bias_fuse(const float* __restrict__ sa_o_b,
                          const float* __restrict__ ta_o_b,
                          const float* __restrict__ fuse_w,
                          const float* __restrict__ fuse_b,
                          float* __restrict__ beff)
{
    int n = blockIdx.x * blockDim.x + threadIdx.x;
    if (n >= D_) return;
    float acc = fuse_b[n];
    for (int k = 0; k < D_; ++k)
        acc += sa_o_b[k] * fuse_w[(size_t)k * D_ + n];
    for (int k = 0; k < D_; ++k)
        acc += ta_o_b[k] * fuse_w[(size_t)(D_ + k) * D_ + n];
    beff[n] = acc;
}

// ---------------------------------------------------------------------------
// Spatial attention: L = CLIP = 8, one block per (b, nc), thread = (head, row).
// QKV layout: (B*S, D) row-major, D index = h*64 + k.
// ---------------------------------------------------------------------------
__global__ __launch_bounds__(128)
void spatial_attn(const float* __restrict__ Q, const float* __restrict__ Kt,
                  const float* __restrict__ Vt, const int* __restrict__ mask,
                  float* __restrict__ O)
{
    const int bn = blockIdx.x;          // b*NC + nc
    const int b  = bn >> 8;             // NC = 256
    const int nc = bn & 255;
    const int t  = threadIdx.x;
    const int h  = t >> 3;
    const int i  = t & 7;
    const size_t base = (size_t)bn * (CLIP_ * D_) + (size_t)h * DK_;

    float q[DK_];
    {
        const float4* qp = (const float4*)(Q + base + (size_t)i * D_);
#pragma unroll
        for (int k4 = 0; k4 < 16; ++k4) {
            float4 v = qp[k4];
            q[4*k4+0] = v.x; q[4*k4+1] = v.y; q[4*k4+2] = v.z; q[4*k4+3] = v.w;
        }
    }

    float s[CLIP_];
#pragma unroll
    for (int j = 0; j < CLIP_; ++j) {
        const float4* kp = (const float4*)(Kt + base + (size_t)j * D_);
        float a0 = 0.f, a1 = 0.f, a2 = 0.f, a3 = 0.f;
#pragma unroll
        for (int k4 = 0; k4 < 16; ++k4) {
            float4 kv = kp[k4];
            a0 += q[4*k4+0] * kv.x;
            a1 += q[4*k4+1] * kv.y;
            a2 += q[4*k4+2] * kv.z;
            a3 += q[4*k4+3] * kv.w;
        }
        float sc = ((a0 + a1) + (a2 + a3)) * 0.125f;
        if (mask[b * S_ + nc * CLIP_ + j] == 0) sc = -1e30f;
        s[j] = sc;
    }

    float mx = s[0];
#pragma unroll
    for (int j = 1; j < CLIP_; ++j) mx = fmaxf(mx, s[j]);
    float l = 0.f;
#pragma unroll
    for (int j = 0; j < CLIP_; ++j) { s[j] = __expf(s[j] - mx); l += s[j]; }
    const float inv = 1.f / l;

    float o[DK_];
#pragma unroll
    for (int k = 0; k < DK_; ++k) o[k] = 0.f;
#pragma unroll
    for (int j = 0; j < CLIP_; ++j) {
        const float p = s[j] * inv;
        const float4* vp = (const float4*)(Vt + base + (size_t)j * D_);
#pragma unroll
        for (int k4 = 0; k4 < 16; ++k4) {
            float4 vv = vp[k4];
            o[4*k4+0] += p * vv.x;
            o[4*k4+1] += p * vv.y;
            o[4*k4+2] += p * vv.z;
            o[4*k4+3] += p * vv.w;
        }
    }

    float4* op = (float4*)(O + base + (size_t)i * D_);
#pragma unroll
    for (int k4 = 0; k4 < 16; ++k4)
        op[k4] = make_float4(o[4*k4+0], o[4*k4+1], o[4*k4+2], o[4*k4+3]);
}

// ---------------------------------------------------------------------------
// Temporal attention: L = NC = 256, one block per (b, clip, h), 256 threads.
// Thread t owns query row nc = t. K/V streamed through smem in 64-row chunks,
// online softmax per thread.
// ---------------------------------------------------------------------------
__global__ __launch_bounds__(256)
void temporal_attn(const float* __restrict__ Q, const float* __restrict__ Kt,
                   const float* __restrict__ Vt, const int* __restrict__ mask,
                   float* __restrict__ O)
{
    __shared__ float Ks[64][68];
    __shared__ float Vs[64][68];

    const int idx  = blockIdx.x;        // (b*CLIP + clip)*H + h
    const int h    = idx & 15;
    const int bc   = idx >> 4;
    const int clip = bc & 7;
    const int b    = bc >> 3;
    const int t    = threadIdx.x;       // query row nc

    const size_t prob    = ((size_t)b * S_ + clip) * D_ + (size_t)h * DK_;
    const size_t rstride = (size_t)CLIP_ * D_;   // 8192 floats between nc rows

    float q[DK_];
    {
        const float4* qp = (const float4*)(Q + prob + (size_t)t * rstride);
#pragma unroll
        for (int k4 = 0; k4 < 16; ++k4) {
            float4 v = qp[k4];
            q[4*k4+0] = v.x; q[4*k4+1] = v.y; q[4*k4+2] = v.z; q[4*k4+3] = v.w;
        }
    }

    float mrun = -1e30f, l = 0.f;
    float acc[DK_];
#pragma unroll
    for (int k = 0; k < DK_; ++k) acc[k] = 0.f;

    const int r  = t >> 2;            // chunk row this thread stages
    const int cp = (t & 3) * 16;      // 16-float slice within the row
    const int* mrow = mask + b * S_ + clip;

#pragma unroll 1
    for (int j0 = 0; j0 < NC_; j0 += 64) {
        __syncthreads();
        {
            const float* ksrc = Kt + prob + (size_t)(j0 + r) * rstride + cp;
            const float* vsrc = Vt + prob + (size_t)(j0 + r) * rstride + cp;
            float4 ka = *(const float4*)(ksrc + 0);
            float4 kb = *(const float4*)(ksrc + 4);
            float4 kc = *(const float4*)(ksrc + 8);
            float4 kd = *(const float4*)(ksrc + 12);
            *(float4*)&Ks[r][cp + 0]  = ka;
            *(float4*)&Ks[r][cp + 4]  = kb;
            *(float4*)&Ks[r][cp + 8]  = kc;
            *(float4*)&Ks[r][cp + 12] = kd;
            float4 va = *(const float4*)(vsrc + 0);
            float4 vb = *(const float4*)(vsrc + 4);
            float4 vc = *(const float4*)(vsrc + 8);
            float4 vd = *(const float4*)(vsrc + 12);
            *(float4*)&Vs[r][cp + 0]  = va;
            *(float4*)&Vs[r][cp + 4]  = vb;
            *(float4*)&Vs[r][cp + 8]  = vc;
            *(float4*)&Vs[r][cp + 12] = vd;
        }
        __syncthreads();

#pragma unroll 1
        for (int j = 0; j < 64; ++j) {
            float a0 = 0.f, a1 = 0.f, a2 = 0.f, a3 = 0.f;
#pragma unroll
            for (int k = 0; k < DK_; k += 4) {
                a0 += q[k + 0] * Ks[j][k + 0];
                a1 += q[k + 1] * Ks[j][k + 1];
                a2 += q[k + 2] * Ks[j][k + 2];
                a3 += q[k + 3] * Ks[j][k + 3];
            }
            float sc = ((a0 + a1) + (a2 + a3)) * 0.125f;
            if (mrow[(j0 + j) * CLIP_] == 0) sc = -1e30f;
            const float mnew = fmaxf(mrun, sc);
            const float corr = __expf(mrun - mnew);
            const float p    = __expf(sc - mnew);
            l = l * corr + p;
#pragma unroll
            for (int k = 0; k < DK_; ++k)
                acc[k] = acc[k] * corr + p * Vs[j][k];
            mrun = mnew;
        }
    }

    const float inv = 1.f / l;
    float4* op = (float4*)(O + prob + (size_t)t * rstride);
#pragma unroll
    for (int k4 = 0; k4 < 16; ++k4)
        op[k4] = make_float4(acc[4*k4+0] * inv, acc[4*k4+1] * inv,
                             acc[4*k4+2] * inv, acc[4*k4+3] * inv);
}

// ---------------------------------------------------------------------------
extern "C" void kernel_launch(void* const* d_in, const int* in_sizes, int n_in,
                              void* d_out, int out_size)
{
    (void)in_sizes; (void)n_in; (void)out_size;

    const float* x      = (const float*)d_in[0];
    const int*   mask   = (const int*)  d_in[1];
    const float* sa_q_w = (const float*)d_in[2];
    const float* sa_q_b = (const float*)d_in[3];
    const float* sa_k_w = (const float*)d_in[4];
    const float* sa_k_b = (const float*)d_in[5];
    const float* sa_v_w = (const float*)d_in[6];
    const float* sa_v_b = (const float*)d_in[7];
    const float* sa_o_w = (const float*)d_in[8];
    const float* sa_o_b = (const float*)d_in[9];
    const float* ta_q_w = (const float*)d_in[10];
    const float* ta_q_b = (const float*)d_in[11];
    const float* ta_k_w = (const float*)d_in[12];
    const float* ta_k_b = (const float*)d_in[13];
    const float* ta_v_w = (const float*)d_in[14];
    const float* ta_v_b = (const float*)d_in[15];
    const float* ta_o_w = (const float*)d_in[16];
    const float* ta_o_b = (const float*)d_in[17];
    const float* fuse_w = (const float*)d_in[18];
    const float* fuse_b = (const float*)d_in[19];
    float* out = (float*)d_out;

    float *sq, *sk, *sv, *tq, *tk, *tv, *sa, *ta, *m1, *m2, *beff;
    cudaGetSymbolAddress((void**)&sq,   g_sq);
    cudaGetSymbolAddress((void**)&sk,   g_sk);
    cudaGetSymbolAddress((void**)&sv,   g_sv);
    cudaGetSymbolAddress((void**)&tq,   g_tq);
    cudaGetSymbolAddress((void**)&tk,   g_tk);
    cudaGetSymbolAddress((void**)&tv,   g_tv);
    cudaGetSymbolAddress((void**)&sa,   g_sa);
    cudaGetSymbolAddress((void**)&ta,   g_ta);
    cudaGetSymbolAddress((void**)&m1,   g_m1);
    cudaGetSymbolAddress((void**)&m2,   g_m2);
    cudaGetSymbolAddress((void**)&beff, g_beff);

    const dim3 blk(256);
    const dim3 gBig(D_ / 128, (B_ * S_) / 128);   // (8, 256)
    const dim3 gSmall(D_ / 128, D_ / 128);        // (8, 8)

    // Folded output-projection x fuse weights: M1 = sa_o_w @ fuse_top,
    // M2 = ta_o_w @ fuse_bot, b_eff = fuse_b + sa_o_b@fuse_top + ta_o_b@fuse_bot
    gemm128<<<gSmall, blk>>>(sa_o_w, fuse_w,                    nullptr, nullptr, m1, D_, D_, D_);
    gemm128<<<gSmall, blk>>>(ta_o_w, fuse_w + (size_t)D_ * D_,  nullptr, nullptr, m2, D_, D_, D_);
    bias_fuse<<<D_ / 256, 256>>>(sa_o_b, ta_o_b, fuse_w, fuse_b, beff);

    // QKV projections (both attentions share input x)
    gemm128<<<gBig, blk>>>(x, sa_q_w, sa_q_b, nullptr, sq, B_ * S_, D_, D_);
    gemm128<<<gBig, blk>>>(x, sa_k_w, sa_k_b, nullptr, sk, B_ * S_, D_, D_);
    gemm128<<<gBig, blk>>>(x, sa_v_w, sa_v_b, nullptr, sv, B_ * S_, D_, D_);
    gemm128<<<gBig, blk>>>(x, ta_q_w, ta_q_b, nullptr, tq, B_ * S_, D_, D_);
    gemm128<<<gBig, blk>>>(x, ta_k_w, ta_k_b, nullptr, tk, B_ * S_, D_, D_);
    gemm128<<<gBig, blk>>>(x, ta_v_w, ta_v_b, nullptr, tv, B_ * S_, D_, D_);

    // Attentions
    spatial_attn<<<B_ * NC_, 128>>>(sq, sk, sv, mask, sa);
    temporal_attn<<<B_ * CLIP_ * H_, 256>>>(tq, tk, tv, mask, ta);

    // Final fused output: out = sa @ M1 + b_eff + ta @ M2
    gemm128<<<gBig, blk>>>(sa, m1, beff, nullptr, out, B_ * S_, D_, D_);
    gemm128<<<gBig, blk>>>(ta, m2, nullptr, out,  out, B_ * S_, D_, D_);
}

// round 7
// speedup vs baseline: 2.2315x; 2.2315x over previous
#include <cuda_runtime.h>
#include <cstdint>
#include <math.h>

// Problem constants
#define B_    16
#define S_    2048
#define D_    1024
#define H_    16
#define CLIP_ 8
#define NC_   256
#define DK_   64

static const size_t TOK   = (size_t)B_ * S_;   // 32768 tokens
static const size_t ELEMS = TOK * D_;          // 33,554,432 floats

// ---------------------------------------------------------------------------
// Scratch (__device__ globals — sanctioned alloc-free scratch)
// ---------------------------------------------------------------------------
__device__ float g_sq[ELEMS];
__device__ float g_sk[ELEMS];
__device__ float g_sv[ELEMS];
__device__ float g_tq[ELEMS];
__device__ float g_tk[ELEMS];
__device__ float g_tv[ELEMS];
__device__ float g_sa[ELEMS];
__device__ float g_ta[ELEMS];
__device__ float g_wt[6u * 1024u * 1024u];   // transposed qkv weights (K-major)
__device__ float g_ft[1024 * 1024];          // fuse_w top half, transposed
__device__ float g_fb[1024 * 1024];          // fuse_w bottom half, transposed
__device__ float g_m1t[1024 * 1024];         // (sa_o_w @ fuse_top)^T
__device__ float g_m2t[1024 * 1024];         // (ta_o_w @ fuse_bot)^T
__device__ float g_beff[D_];

// ---------------------------------------------------------------------------
// tf32 helpers (baseline PTX — no 'a'-gated features)
// ---------------------------------------------------------------------------
__device__ __forceinline__ uint32_t f2tf32(float x) {
    uint32_t r;
    asm("cvt.rna.tf32.f32 %0, %1;" : "=r"(r) : "f"(x));
    return r;
}
__device__ __forceinline__ void mma16n8k8(float* d, const uint32_t* a, const uint32_t* b) {
    asm volatile(
        "mma.sync.aligned.m16n8k8.row.col.f32.tf32.tf32.f32 "
        "{%0,%1,%2,%3}, {%4,%5,%6,%7}, {%8,%9}, {%0,%1,%2,%3};"
        : "+f"(d[0]), "+f"(d[1]), "+f"(d[2]), "+f"(d[3])
        : "r"(a[0]), "r"(a[1]), "r"(a[2]), "r"(a[3]), "r"(b[0]), "r"(b[1]));
}
__device__ __forceinline__ uint32_t smem_u32(const void* p) {
    uint32_t a;
    asm("{ .reg .u64 t; cvta.to.shared.u64 t, %1; cvt.u32.u64 %0, t; }" : "=r"(a) : "l"(p));
    return a;
}
__device__ __forceinline__ void cp16(uint32_t dst, const void* src) {
    asm volatile("cp.async.cg.shared.global [%0], [%1], 16;" :: "r"(dst), "l"(src) : "memory");
}

// ---------------------------------------------------------------------------
// tf32 tensor-core GEMM:  C[M,N] = [A | A2][M, K] @ [BT | BT2]^T (+bias)
// BT tensors are [N, K-part] row-major (K-major).  All row strides = 1024.
// Block tile 128x128, BK=16, 256 threads (8 warps, 2m x 4n of 64x32),
// cp.async double-buffered STATIC smem (40 KB total — no dynamic smem,
// no cudaFuncSetAttribute).
// ---------------------------------------------------------------------------
#define PAD_ 20                            // 16 + 4 pad: conflict-free fragments

__global__ void __launch_bounds__(256, 2)
gemm_tf32(const float* __restrict__ A, const float* __restrict__ A2,
          const float* __restrict__ BT, const float* __restrict__ BT2,
          const float* __restrict__ bias,
          float* __restrict__ C, int N, int K, int Ksplit)
{
    __shared__ float sA[2][128][PAD_];
    __shared__ float sB[2][128][PAD_];

    const int tid  = threadIdx.x;
    const int wid  = tid >> 5;
    const int lane = tid & 31;
    const int grp  = lane >> 2;
    const int tig  = lane & 3;
    const int wm   = wid & 1;             // 0..1  -> 64-row half
    const int wn   = wid >> 1;            // 0..3  -> 32-col quarter
    const int bx = blockIdx.x, by = blockIdx.y;

    // staging: thread copies 8 floats of one A row and one B row per stage
    const int srow  = tid >> 1;           // 0..127
    const int shalf = (tid & 1) * 8;      // 0 or 8
    const size_t aOff = (size_t)(by * 128 + srow) * 1024 + shalf;
    const size_t bOff = (size_t)(bx * 128 + srow) * 1024 + shalf;
    const uint32_t sAaddr = smem_u32(&sA[0][srow][shalf]);
    const uint32_t sBaddr = smem_u32(&sB[0][srow][shalf]);
    const uint32_t bufBytes = 128u * PAD_ * 4u;

    float acc[4][4][4];
#pragma unroll
    for (int mt = 0; mt < 4; ++mt)
#pragma unroll
        for (int nt = 0; nt < 4; ++nt)
#pragma unroll
            for (int r = 0; r < 4; ++r) acc[mt][nt][r] = 0.f;

    const int nStages = K / 16;

    // prefetch stage 0 (k=0 always < Ksplit)
    {
        const float* as = A + aOff;
        const float* bs = BT + bOff;
        cp16(sAaddr,       as);
        cp16(sAaddr + 16u, as + 4);
        cp16(sBaddr,       bs);
        cp16(sBaddr + 16u, bs + 4);
        asm volatile("cp.async.commit_group;" ::: "memory");
    }

#pragma unroll 1
    for (int s = 0; s < nStages; ++s) {
        const int buf = s & 1;
        if (s + 1 < nStages) {
            const int k1 = (s + 1) * 16;
            const float* as; const float* bs;
            if (k1 < Ksplit) { as = A  + aOff + k1;          bs = BT  + bOff + k1; }
            else             { as = A2 + aOff + k1 - Ksplit; bs = BT2 + bOff + k1 - Ksplit; }
            const uint32_t db = (uint32_t)(buf ^ 1) * bufBytes;
            cp16(sAaddr + db,       as);
            cp16(sAaddr + db + 16u, as + 4);
            cp16(sBaddr + db,       bs);
            cp16(sBaddr + db + 16u, bs + 4);
            asm volatile("cp.async.commit_group;" ::: "memory");
            asm volatile("cp.async.wait_group 1;" ::: "memory");
        } else {
            asm volatile("cp.async.wait_group 0;" ::: "memory");
        }
        __syncthreads();

        const float (*Ab)[PAD_] = sA[buf];
        const float (*Bb)[PAD_] = sB[buf];
#pragma unroll
        for (int kk = 0; kk < 2; ++kk) {
            const int kc = kk * 8 + tig;
            uint32_t af[4][4];
#pragma unroll
            for (int mt = 0; mt < 4; ++mt) {
                const int r0 = wm * 64 + mt * 16 + grp;
                af[mt][0] = f2tf32(Ab[r0][kc]);
                af[mt][1] = f2tf32(Ab[r0 + 8][kc]);
                af[mt][2] = f2tf32(Ab[r0][kc + 4]);
                af[mt][3] = f2tf32(Ab[r0 + 8][kc + 4]);
            }
            uint32_t bf[4][2];
#pragma unroll
            for (int nt = 0; nt < 4; ++nt) {
                const int n0 = wn * 32 + nt * 8 + grp;
                bf[nt][0] = f2tf32(Bb[n0][kc]);
                bf[nt][1] = f2tf32(Bb[n0][kc + 4]);
            }
#pragma unroll
            for (int mt = 0; mt < 4; ++mt)
#pragma unroll
                for (int nt = 0; nt < 4; ++nt)
                    mma16n8k8(acc[mt][nt], af[mt], bf[nt]);
        }
        __syncthreads();
    }

    // Epilogue
    const int mBase = by * 128 + wm * 64;
    const int nBase = bx * 128 + wn * 32;
#pragma unroll
    for (int nt = 0; nt < 4; ++nt) {
        const int col = nBase + nt * 8 + tig * 2;
        float2 bsv = make_float2(0.f, 0.f);
        if (bias) bsv = *(const float2*)(bias + col);
#pragma unroll
        for (int mt = 0; mt < 4; ++mt) {
            const int r0 = mBase + mt * 16 + grp;
            float2* p0 = (float2*)(C + (size_t)r0 * N + col);
            float2* p1 = (float2*)(C + (size_t)(r0 + 8) * N + col);
            *p0 = make_float2(acc[mt][nt][0] + bsv.x, acc[mt][nt][1] + bsv.y);
            *p1 = make_float2(acc[mt][nt][2] + bsv.x, acc[mt][nt][3] + bsv.y);
        }
    }
}

// ---------------------------------------------------------------------------
// 1024x1024 fp32 transpose
// ---------------------------------------------------------------------------
__global__ __launch_bounds__(256)
void transpose1024(const float* __restrict__ src, float* __restrict__ dst)
{
    __shared__ float t[32][33];
    const int bx = blockIdx.x * 32, by = blockIdx.y * 32;
    const int tx = threadIdx.x, ty = threadIdx.y;   // 32 x 8
#pragma unroll
    for (int j = 0; j < 32; j += 8)
        t[ty + j][tx] = src[(size_t)(by + ty + j) * 1024 + bx + tx];
    __syncthreads();
#pragma unroll
    for (int j = 0; j < 32; j += 8)
        dst[(size_t)(bx + ty + j) * 1024 + by + tx] = t[tx][ty + j];
}

// ---------------------------------------------------------------------------
// Effective fuse bias
// ---------------------------------------------------------------------------
__global__ void bias_fuse(const float* __restrict__ sa_o_b,
                          const float* __restrict__ ta_o_b,
                          const float* __restrict__ fuse_w,
                          const float* __restrict__ fuse_b,
                          float* __restrict__ beff)
{
    int n = blockIdx.x * blockDim.x + threadIdx.x;
    if (n >= D_) return;
    float acc = fuse_b[n];
    for (int k = 0; k < D_; ++k)
        acc += sa_o_b[k] * fuse_w[(size_t)k * D_ + n];
    for (int k = 0; k < D_; ++k)
        acc += ta_o_b[k] * fuse_w[(size_t)(D_ + k) * D_ + n];
    beff[n] = acc;
}

// ---------------------------------------------------------------------------
// Spatial attention: L = CLIP = 8
// ---------------------------------------------------------------------------
__global__ __launch_bounds__(128)
void spatial_attn(const float* __restrict__ Q, const float* __restrict__ Kt,
                  const float* __restrict__ Vt, const int* __restrict__ mask,
                  float* __restrict__ O)
{
    const int bn = blockIdx.x;
    const int b  = bn >> 8;
    const int nc = bn & 255;
    const int t  = threadIdx.x;
    const int h  = t >> 3;
    const int i  = t & 7;
    const size_t base = (size_t)bn * (CLIP_ * D_) + (size_t)h * DK_;

    float q[DK_];
    {
        const float4* qp = (const float4*)(Q + base + (size_t)i * D_);
#pragma unroll
        for (int k4 = 0; k4 < 16; ++k4) {
            float4 v = qp[k4];
            q[4*k4+0] = v.x; q[4*k4+1] = v.y; q[4*k4+2] = v.z; q[4*k4+3] = v.w;
        }
    }
    float s[CLIP_];
#pragma unroll
    for (int j = 0; j < CLIP_; ++j) {
        const float4* kp = (const float4*)(Kt + base + (size_t)j * D_);
        float a0 = 0.f, a1 = 0.f, a2 = 0.f, a3 = 0.f;
#pragma unroll
        for (int k4 = 0; k4 < 16; ++k4) {
            float4 kv = kp[k4];
            a0 += q[4*k4+0] * kv.x; a1 += q[4*k4+1] * kv.y;
            a2 += q[4*k4+2] * kv.z; a3 += q[4*k4+3] * kv.w;
        }
        float sc = ((a0 + a1) + (a2 + a3)) * 0.125f;
        if (mask[b * S_ + nc * CLIP_ + j] == 0) sc = -1e30f;
        s[j] = sc;
    }
    float mx = s[0];
#pragma unroll
    for (int j = 1; j < CLIP_; ++j) mx = fmaxf(mx, s[j]);
    float l = 0.f;
#pragma unroll
    for (int j = 0; j < CLIP_; ++j) { s[j] = __expf(s[j] - mx); l += s[j]; }
    const float inv = 1.f / l;

    float o[DK_];
#pragma unroll
    for (int k = 0; k < DK_; ++k) o[k] = 0.f;
#pragma unroll
    for (int j = 0; j < CLIP_; ++j) {
        const float p = s[j] * inv;
        const float4* vp = (const float4*)(Vt + base + (size_t)j * D_);
#pragma unroll
        for (int k4 = 0; k4 < 16; ++k4) {
            float4 vv = vp[k4];
            o[4*k4+0] += p * vv.x; o[4*k4+1] += p * vv.y;
            o[4*k4+2] += p * vv.z; o[4*k4+3] += p * vv.w;
        }
    }
    float4* op = (float4*)(O + base + (size_t)i * D_);
#pragma unroll
    for (int k4 = 0; k4 < 16; ++k4)
        op[k4] = make_float4(o[4*k4+0], o[4*k4+1], o[4*k4+2], o[4*k4+3]);
}

// ---------------------------------------------------------------------------
// Temporal attention: L = NC = 256
// ---------------------------------------------------------------------------
__global__ __launch_bounds__(256)
void temporal_attn(const float* __restrict__ Q, const float* __restrict__ Kt,
                   const float* __restrict__ Vt, const int* __restrict__ mask,
                   float* __restrict__ O)
{
    __shared__ float Ks[64][68];
    __shared__ float Vs[64][68];

    const int idx  = blockIdx.x;
    const int h    = idx & 15;
    const int bc   = idx >> 4;
    const int clip = bc & 7;
    const int b    = bc >> 3;
    const int t    = threadIdx.x;

    const size_t prob    = ((size_t)b * S_ + clip) * D_ + (size_t)h * DK_;
    const size_t rstride = (size_t)CLIP_ * D_;

    float q[DK_];
    {
        const float4* qp = (const float4*)(Q + prob + (size_t)t * rstride);
#pragma unroll
        for (int k4 = 0; k4 < 16; ++k4) {
            float4 v = qp[k4];
            q[4*k4+0] = v.x; q[4*k4+1] = v.y; q[4*k4+2] = v.z; q[4*k4+3] = v.w;
        }
    }
    float mrun = -1e30f, l = 0.f;
    float acc[DK_];
#pragma unroll
    for (int k = 0; k < DK_; ++k) acc[k] = 0.f;

    const int r  = t >> 2;
    const int cp = (t & 3) * 16;
    const int* mrow = mask + b * S_ + clip;

#pragma unroll 1
    for (int j0 = 0; j0 < NC_; j0 += 64) {
        __syncthreads();
        {
            const float* ksrc = Kt + prob + (size_t)(j0 + r) * rstride + cp;
            const float* vsrc = Vt + prob + (size_t)(j0 + r) * rstride + cp;
            float4 ka = *(const float4*)(ksrc + 0);
            float4 kb = *(const float4*)(ksrc + 4);
            float4 kc = *(const float4*)(ksrc + 8);
            float4 kd = *(const float4*)(ksrc + 12);
            *(float4*)&Ks[r][cp + 0]  = ka;
            *(float4*)&Ks[r][cp + 4]  = kb;
            *(float4*)&Ks[r][cp + 8]  = kc;
            *(float4*)&Ks[r][cp + 12] = kd;
            float4 va = *(const float4*)(vsrc + 0);
            float4 vb = *(const float4*)(vsrc + 4);
            float4 vc = *(const float4*)(vsrc + 8);
            float4 vd = *(const float4*)(vsrc + 12);
            *(float4*)&Vs[r][cp + 0]  = va;
            *(float4*)&Vs[r][cp + 4]  = vb;
            *(float4*)&Vs[r][cp + 8]  = vc;
            *(float4*)&Vs[r][cp + 12] = vd;
        }
        __syncthreads();

#pragma unroll 1
        for (int j = 0; j < 64; ++j) {
            float a0 = 0.f, a1 = 0.f, a2 = 0.f, a3 = 0.f;
#pragma unroll
            for (int k = 0; k < DK_; k += 4) {
                a0 += q[k + 0] * Ks[j][k + 0];
                a1 += q[k + 1] * Ks[j][k + 1];
                a2 += q[k + 2] * Ks[j][k + 2];
                a3 += q[k + 3] * Ks[j][k + 3];
            }
            float sc = ((a0 + a1) + (a2 + a3)) * 0.125f;
            if (mrow[(j0 + j) * CLIP_] == 0) sc = -1e30f;
            const float mnew = fmaxf(mrun, sc);
            const float corr = __expf(mrun - mnew);
            const float p    = __expf(sc - mnew);
            l = l * corr + p;
#pragma unroll
            for (int k = 0; k < DK_; ++k)
                acc[k] = acc[k] * corr + p * Vs[j][k];
            mrun = mnew;
        }
    }
    const float inv = 1.f / l;
    float4* op = (float4*)(O + prob + (size_t)t * rstride);
#pragma unroll
    for (int k4 = 0; k4 < 16; ++k4)
        op[k4] = make_float4(acc[4*k4+0] * inv, acc[4*k4+1] * inv,
                             acc[4*k4+2] * inv, acc[4*k4+3] * inv);
}

// ---------------------------------------------------------------------------
extern "C" void kernel_launch(void* const* d_in, const int* in_sizes, int n_in,
                              void* d_out, int out_size)
{
    (void)in_sizes; (void)n_in; (void)out_size;

    const float* x      = (const float*)d_in[0];
    const int*   mask   = (const int*)  d_in[1];
    const float* sa_q_w = (const float*)d_in[2];
    const float* sa_q_b = (const float*)d_in[3];
    const float* sa_k_w = (const float*)d_in[4];
    const float* sa_k_b = (const float*)d_in[5];
    const float* sa_v_w = (const float*)d_in[6];
    const float* sa_v_b = (const float*)d_in[7];
    const float* sa_o_w = (const float*)d_in[8];
    const float* sa_o_b = (const float*)d_in[9];
    const float* ta_q_w = (const float*)d_in[10];
    const float* ta_q_b = (const float*)d_in[11];
    const float* ta_k_w = (const float*)d_in[12];
    const float* ta_k_b = (const float*)d_in[13];
    const float* ta_v_w = (const float*)d_in[14];
    const float* ta_v_b = (const float*)d_in[15];
    const float* ta_o_w = (const float*)d_in[16];
    const float* ta_o_b = (const float*)d_in[17];
    const float* fuse_w = (const float*)d_in[18];
    const float* fuse_b = (const float*)d_in[19];
    float* out = (float*)d_out;

    float *sq, *sk, *sv, *tq, *tk, *tv, *sa, *ta, *wt, *ft, *fb, *m1t, *m2t, *beff;
    cudaGetSymbolAddress((void**)&sq,   g_sq);
    cudaGetSymbolAddress((void**)&sk,   g_sk);
    cudaGetSymbolAddress((void**)&sv,   g_sv);
    cudaGetSymbolAddress((void**)&tq,   g_tq);
    cudaGetSymbolAddress((void**)&tk,   g_tk);
    cudaGetSymbolAddress((void**)&tv,   g_tv);
    cudaGetSymbolAddress((void**)&sa,   g_sa);
    cudaGetSymbolAddress((void**)&ta,   g_ta);
    cudaGetSymbolAddress((void**)&wt,   g_wt);
    cudaGetSymbolAddress((void**)&ft,   g_ft);
    cudaGetSymbolAddress((void**)&fb,   g_fb);
    cudaGetSymbolAddress((void**)&m1t,  g_m1t);
    cudaGetSymbolAddress((void**)&m2t,  g_m2t);
    cudaGetSymbolAddress((void**)&beff, g_beff);

    const size_t MM = 1024u * 1024u;
    const dim3 tb(32, 8);
    const dim3 tg(32, 32);

    // Transpose weights to K-major ([N,K]) for the B operand
    transpose1024<<<tg, tb>>>(sa_q_w, wt + 0 * MM);
    transpose1024<<<tg, tb>>>(sa_k_w, wt + 1 * MM);
    transpose1024<<<tg, tb>>>(sa_v_w, wt + 2 * MM);
    transpose1024<<<tg, tb>>>(ta_q_w, wt + 3 * MM);
    transpose1024<<<tg, tb>>>(ta_k_w, wt + 4 * MM);
    transpose1024<<<tg, tb>>>(ta_v_w, wt + 5 * MM);
    transpose1024<<<tg, tb>>>(fuse_w,      ft);
    transpose1024<<<tg, tb>>>(fuse_w + MM, fb);

    bias_fuse<<<D_ / 256, 256>>>(sa_o_b, ta_o_b, fuse_w, fuse_b, beff);

    // Folded weights: m1t[i][j] = sum_k ft[i][k] * sa_o_w[j][k]
    const dim3 gSmall(8, 8);
    gemm_tf32<<<gSmall, 256>>>(ft, ft, sa_o_w, sa_o_w, nullptr, m1t, 1024, 1024, 1024);
    gemm_tf32<<<gSmall, 256>>>(fb, fb, ta_o_w, ta_o_w, nullptr, m2t, 1024, 1024, 1024);

    // QKV projections
    const dim3 gBig(8, 256);
    gemm_tf32<<<gBig, 256>>>(x, x, wt + 0 * MM, wt + 0 * MM, sa_q_b, sq, D_, D_, D_);
    gemm_tf32<<<gBig, 256>>>(x, x, wt + 1 * MM, wt + 1 * MM, sa_k_b, sk, D_, D_, D_);
    gemm_tf32<<<gBig, 256>>>(x, x, wt + 2 * MM, wt + 2 * MM, sa_v_b, sv, D_, D_, D_);
    gemm_tf32<<<gBig, 256>>>(x, x, wt + 3 * MM, wt + 3 * MM, ta_q_b, tq, D_, D_, D_);
    gemm_tf32<<<gBig, 256>>>(x, x, wt + 4 * MM, wt + 4 * MM, ta_k_b, tk, D_, D_, D_);
    gemm_tf32<<<gBig, 256>>>(x, x, wt + 5 * MM, wt + 5 * MM, ta_v_b, tv, D_, D_, D_);

    // Attentions
    spatial_attn<<<B_ * NC_, 128>>>(sq, sk, sv, mask, sa);
    temporal_attn<<<B_ * CLIP_ * H_, 256>>>(tq, tk, tv, mask, ta);

    // Fused final: out = sa @ m1 + ta @ m2 + beff   (single K=2048 pass)
    gemm_tf32<<<gBig, 256>>>(sa, ta, m1t, m2t, beff, out, D_, 2048, 1024);
}